// round 1
// baseline (speedup 1.0000x reference)
#include <cuda_runtime.h>
#include <math.h>

// ---------------------------------------------------------------------------
// Problem dims
// ---------------------------------------------------------------------------
#define D_    2048
#define V_    2048
#define LSEQ  512
#define LP1   513          // L + 1
#define T_    65           // decode steps = P + 1
#define G4    8192         // 4*D
#define ROWS_TOT 10240     // G4 (gates) + V_ (d rows)

#define NB    148          // persistent blocks (<= SM count)
#define NT    512          // threads per block
#define NW    16           // warps per block
#define TOTW  (NB*NW)

// ---------------------------------------------------------------------------
// Device scratch (static: no allocations allowed)
// ---------------------------------------------------------------------------
__device__ float g_enc[LP1 * V_];        // enc_proj  [513][2048]  (4.2 MB)
__device__ float g_gates[2][G4];         // double-buffered LSTM gates
__device__ float g_dall[T_][V_];         // d_t = Wd@h_t + Wd_b for all steps
__device__ unsigned g_barcnt;            // grid barrier count (returns to 0)
__device__ volatile unsigned g_bargen;   // grid barrier generation

// ---------------------------------------------------------------------------
// Grid barrier (all NB blocks co-resident: 1 block/SM by construction)
// ---------------------------------------------------------------------------
__device__ __forceinline__ void gridbar() {
    __syncthreads();
    if (threadIdx.x == 0) {
        __threadfence();                       // publish my writes (flushes L1 on sm_103a)
        unsigned gen = g_bargen;
        if (atomicAdd(&g_barcnt, 1u) == NB - 1u) {
            atomicExch(&g_barcnt, 0u);
            __threadfence();
            g_bargen = gen + 1u;
        } else {
            while (g_bargen == gen) { }
        }
        __threadfence();                       // acquire
    }
    __syncthreads();
}

__device__ __forceinline__ float sigmoidf_(float x) {
    return 1.0f / (1.0f + expf(-x));
}

// ---------------------------------------------------------------------------
// Shared memory: stage-disjoint union
// ---------------------------------------------------------------------------
struct S0 {                       // stage 0: enc_proj GEMM tiles
    float enc[64 * 68];           // [64 l][64 k] stride 68
    float we [64 * 65];           // [64 k][64 v] stride 65 (transposed)
};
struct S1 {                       // stage 1: recurrence state (per-block copy)
    float h[D_];
    float c[D_];
};
struct S2 {                       // stage 2: pointer scoring
    float d [V_];
    float vw[V_];
};

__global__ void __launch_bounds__(NT)
decoder_kernel(const float* __restrict__ initial_state,
               const float* __restrict__ enc_states,
               const float* __restrict__ seq_points,
               const int*   __restrict__ positions,
               const float* __restrict__ W_ih,
               const float* __restrict__ W_hh,
               const float* __restrict__ b_ih,
               const float* __restrict__ b_hh,
               const float* __restrict__ We_w,
               const float* __restrict__ We_b,
               const float* __restrict__ Wd_w,
               const float* __restrict__ Wd_b,
               const float* __restrict__ v_w,
               const float* __restrict__ v_b,
               float* __restrict__ out_logits,   // [65][513]
               float* __restrict__ out_hs,       // [65][2048]
               float* __restrict__ out_losses)   // [65]
{
    __shared__ __align__(16) union { S0 s0; S1 s1; S2 s2; } sm;
    __shared__ float red[NW];

    const int tid  = threadIdx.x;
    const int wid  = tid >> 5;
    const int lane = tid & 31;
    const int gw   = blockIdx.x * NW + wid;   // global warp id

    // =======================================================================
    // Stage 0: enc_proj[l][v] = sum_k enc[l][k] * We_w[v][k] + We_b[v]
    // Tiles 64l x 64v, k-chunks of 64.  288 tiles grid-strided over 148 blocks
    // =======================================================================
    {
        const int ty = tid >> 5;     // 0..15 -> 4 l-rows each
        const int tx = tid & 31;     // v cols: tx and tx+32
        const int ldrow = tid >> 4;  // 0..31 (load mapping)
        const int ldc4  = tid & 15;  // float4 column

        for (int tile = blockIdx.x; tile < 9 * 32; tile += NB) {
            const int lt = tile >> 5;        // 0..8
            const int vt = tile & 31;        // 0..31
            const int l0 = lt * 64;
            const int v0 = vt * 64;

            float acc[4][2];
            #pragma unroll
            for (int i = 0; i < 4; ++i) { acc[i][0] = 0.f; acc[i][1] = 0.f; }

            for (int k0 = 0; k0 < D_; k0 += 64) {
                // load enc tile [64 l][64 k]
                #pragma unroll
                for (int rep = 0; rep < 2; ++rep) {
                    int row = ldrow + rep * 32;
                    int gl  = l0 + row; if (gl > 512) gl = 512;   // clamp (guarded on store)
                    float4 v = *(const float4*)&enc_states[(size_t)gl * D_ + k0 + ldc4 * 4];
                    *(float4*)&sm.s0.enc[row * 68 + ldc4 * 4] = v;
                }
                // load We tile transposed -> [k][v] stride 65
                #pragma unroll
                for (int rep = 0; rep < 2; ++rep) {
                    int vrow = ldrow + rep * 32;            // v offset in tile
                    float4 w = *(const float4*)&We_w[(size_t)(v0 + vrow) * D_ + k0 + ldc4 * 4];
                    sm.s0.we[(ldc4 * 4 + 0) * 65 + vrow] = w.x;
                    sm.s0.we[(ldc4 * 4 + 1) * 65 + vrow] = w.y;
                    sm.s0.we[(ldc4 * 4 + 2) * 65 + vrow] = w.z;
                    sm.s0.we[(ldc4 * 4 + 3) * 65 + vrow] = w.w;
                }
                __syncthreads();

                #pragma unroll 8
                for (int k = 0; k < 64; ++k) {
                    float b0 = sm.s0.we[k * 65 + tx];
                    float b1 = sm.s0.we[k * 65 + tx + 32];
                    #pragma unroll
                    for (int i = 0; i < 4; ++i) {
                        float a = sm.s0.enc[(ty * 4 + i) * 68 + k];
                        acc[i][0] = fmaf(a, b0, acc[i][0]);
                        acc[i][1] = fmaf(a, b1, acc[i][1]);
                    }
                }
                __syncthreads();
            }

            #pragma unroll
            for (int i = 0; i < 4; ++i) {
                int l = l0 + ty * 4 + i;
                if (l < LP1) {
                    g_enc[(size_t)l * V_ + v0 + tx]      = acc[i][0] + We_b[v0 + tx];
                    g_enc[(size_t)l * V_ + v0 + tx + 32] = acc[i][1] + We_b[v0 + tx + 32];
                }
            }
        }
        __syncthreads();
    }

    // =======================================================================
    // Stage 1: LSTM recurrence.  66 iterations, ONE grid barrier each.
    //   iter t: matvec rows -> gates_t (t<=64) and d_{t-1} (t>=1)   [from h]
    //           barrier
    //           redundant per-block elementwise: (c,h) <- lstm(gates_t)
    // =======================================================================
    // init per-block state
    for (int j = tid; j < D_; j += NT) {
        sm.s1.h[j] = initial_state[j];
        sm.s1.c[j] = 0.0f;
    }
    __syncthreads();

    for (int t = 0; t <= T_; ++t) {
        // teacher-forced input x_t
        float x0 = 0.f, x1 = 0.f, x2 = 1.f;
        if (t >= 1 && t <= 64) {
            int pos = positions[t - 1];
            x0 = seq_points[pos * 3 + 0];
            x1 = seq_points[pos * 3 + 1];
            x2 = seq_points[pos * 3 + 2];
        }

        const float4* h4 = (const float4*)sm.s1.h;
        for (int r = gw; r < ROWS_TOT; r += TOTW) {
            const bool isg = (r < G4);
            if (isg && t >= T_) continue;         // last iter: only d rows
            if (!isg && t == 0) continue;         // first iter: no d yet

            const float* wrow = isg ? (W_hh + (size_t)r * D_)
                                    : (Wd_w + (size_t)(r - G4) * D_);
            const float4* w4 = (const float4*)wrow;

            float a0 = 0.f, a1 = 0.f;
            #pragma unroll 4
            for (int k = lane; k < D_ / 4; k += 32) {
                float4 w = w4[k];
                float4 h = h4[k];
                a0 = fmaf(w.x, h.x, a0);
                a1 = fmaf(w.y, h.y, a1);
                a0 = fmaf(w.z, h.z, a0);
                a1 = fmaf(w.w, h.w, a1);
            }
            float acc = a0 + a1;
            #pragma unroll
            for (int off = 16; off > 0; off >>= 1)
                acc += __shfl_down_sync(0xffffffffu, acc, off);

            if (lane == 0) {
                if (isg) {
                    float e = b_ih[r] + b_hh[r]
                            + W_ih[r * 3 + 0] * x0
                            + W_ih[r * 3 + 1] * x1
                            + W_ih[r * 3 + 2] * x2;
                    g_gates[t & 1][r] = acc + e;
                } else {
                    g_dall[t - 1][r - G4] = acc + Wd_b[r - G4];
                }
            }
        }

        gridbar();

        if (t < T_) {
            const float* gp = g_gates[t & 1];
            for (int j = tid; j < D_; j += NT) {
                float gi = __ldcg(gp + j);
                float gf = __ldcg(gp + D_ + j);
                float gg = __ldcg(gp + 2 * D_ + j);
                float go = __ldcg(gp + 3 * D_ + j);
                float i_ = sigmoidf_(gi);
                float f_ = sigmoidf_(gf);
                float g_ = tanhf(gg);
                float o_ = sigmoidf_(go);
                float c  = fmaf(f_, sm.s1.c[j], i_ * g_);
                float h  = o_ * tanhf(c);
                sm.s1.c[j] = c;
                sm.s1.h[j] = h;
                if (blockIdx.x == 0) out_hs[(size_t)t * D_ + j] = h;
            }
            __syncthreads();
        }
    }

    // =======================================================================
    // Stage 2: logits[t][l] = sum_v tanh(enc[l][v] + d_t[v]) * v_w[v] + v_b
    // work items: (t, l-chunk of 57).  65*9 = 585 items grid-strided.
    // =======================================================================
    for (int j = tid; j < V_; j += NT) sm.s2.vw[j] = v_w[j];
    const float vb = v_b[0];

    for (int item = blockIdx.x; item < T_ * 9; item += NB) {
        const int t  = item / 9;
        const int ch = item % 9;
        __syncthreads();
        for (int j = tid; j < V_; j += NT) sm.s2.d[j] = __ldcg(&g_dall[t][j]);
        __syncthreads();

        const int lbase = ch * 57;
        const float4* d4 = (const float4*)sm.s2.d;
        const float4* w4 = (const float4*)sm.s2.vw;
        for (int l = lbase + wid; l < lbase + 57; l += NW) {
            const float4* e4 = (const float4*)(g_enc + (size_t)l * V_);
            float acc = 0.f;
            #pragma unroll 4
            for (int k = lane; k < V_ / 4; k += 32) {
                float4 e = __ldcg(e4 + k);
                float4 d = d4[k];
                float4 w = w4[k];
                acc = fmaf(tanhf(e.x + d.x), w.x, acc);
                acc = fmaf(tanhf(e.y + d.y), w.y, acc);
                acc = fmaf(tanhf(e.z + d.z), w.z, acc);
                acc = fmaf(tanhf(e.w + d.w), w.w, acc);
            }
            #pragma unroll
            for (int off = 16; off > 0; off >>= 1)
                acc += __shfl_down_sync(0xffffffffu, acc, off);
            if (lane == 0) out_logits[(size_t)t * LP1 + l] = acc + vb;
        }
    }

    gridbar();

    // =======================================================================
    // Stage 3: losses[t] = logsumexp(logits_t) - logits_t[target_t]
    // =======================================================================
    if (blockIdx.x < T_) {
        const int t = blockIdx.x;
        const float* lg = out_logits + (size_t)t * LP1;

        float m = -1e30f;
        for (int i = tid; i < LP1; i += NT) m = fmaxf(m, __ldcg(lg + i));
        #pragma unroll
        for (int off = 16; off > 0; off >>= 1)
            m = fmaxf(m, __shfl_down_sync(0xffffffffu, m, off));
        if (lane == 0) red[wid] = m;
        __syncthreads();
        if (wid == 0) {
            float mm = (lane < NW) ? red[lane] : -1e30f;
            #pragma unroll
            for (int off = 16; off > 0; off >>= 1)
                mm = fmaxf(mm, __shfl_down_sync(0xffffffffu, mm, off));
            if (lane == 0) red[0] = mm;
        }
        __syncthreads();
        m = red[0];
        __syncthreads();

        float s = 0.f;
        for (int i = tid; i < LP1; i += NT) s += expf(__ldcg(lg + i) - m);
        #pragma unroll
        for (int off = 16; off > 0; off >>= 1)
            s += __shfl_down_sync(0xffffffffu, s, off);
        if (lane == 0) red[wid] = s;
        __syncthreads();
        if (wid == 0) {
            float ss = (lane < NW) ? red[lane] : 0.f;
            #pragma unroll
            for (int off = 16; off > 0; off >>= 1)
                ss += __shfl_down_sync(0xffffffffu, ss, off);
            if (lane == 0) {
                int tgt = (t < 64) ? positions[t] : LSEQ;
                out_losses[t] = m + logf(ss) - __ldcg(lg + tgt);
            }
        }
    }
}

// ---------------------------------------------------------------------------
// Launch
// ---------------------------------------------------------------------------
extern "C" void kernel_launch(void* const* d_in, const int* in_sizes, int n_in,
                              void* d_out, int out_size) {
    const float* initial_state = (const float*)d_in[0];
    const float* enc_states    = (const float*)d_in[1];
    const float* seq_points    = (const float*)d_in[2];
    const int*   positions     = (const int*)  d_in[3];
    const float* W_ih          = (const float*)d_in[4];
    const float* W_hh          = (const float*)d_in[5];
    const float* b_ih          = (const float*)d_in[6];
    const float* b_hh          = (const float*)d_in[7];
    const float* We_w          = (const float*)d_in[8];
    const float* We_b          = (const float*)d_in[9];
    const float* Wd_w          = (const float*)d_in[10];
    const float* Wd_b          = (const float*)d_in[11];
    const float* v_w           = (const float*)d_in[12];
    const float* v_b           = (const float*)d_in[13];

    float* out        = (float*)d_out;
    float* out_logits = out;                       // 65*513
    float* out_hs     = out + T_ * LP1;            // 65*2048
    float* out_losses = out + T_ * LP1 + T_ * D_;  // 65

    decoder_kernel<<<NB, NT>>>(initial_state, enc_states, seq_points, positions,
                               W_ih, W_hh, b_ih, b_hh, We_w, We_b, Wd_w, Wd_b,
                               v_w, v_b, out_logits, out_hs, out_losses);
}

// round 3
// speedup vs baseline: 1.5826x; 1.5826x over previous
#include <cuda_runtime.h>
#include <cuda_fp16.h>
#include <math.h>

// ---------------------------------------------------------------------------
// Problem dims
// ---------------------------------------------------------------------------
#define D_    2048
#define V_    2048
#define LSEQ  512
#define LP1   513
#define T_    65
#define G4    8192
#define ROWS_TOT 10240        // 4D gate rows + V d-rows

#define NBLK  148             // persistent blocks (all co-resident, 1/SM)
#define NT    1024
#define NW    32
#define NA    64              // blocks doing the recurrence (group A)
                              // blocks NA..147 do the enc GEMM (group B)

// ---------------------------------------------------------------------------
// Device scratch
// ---------------------------------------------------------------------------
// fp16 W_hh (rows 0..8191) + Wd_w (rows 8192..10239): 10240*2048 halves = 40MB.
// One uint2 holds 4 halves -> ROWS_TOT*D_/4 entries.
__device__ uint2 g_w16[(size_t)ROWS_TOT * D_ / 4];
__device__ float g_enc[LP1 * V_];                   // enc_proj
__device__ float g_gates[2][G4];                    // double-buffered gates
__device__ float g_dall[T_][V_];                    // d_t for all steps
__device__ unsigned g_cntA;  __device__ volatile unsigned g_genA;   // group-A barrier
__device__ unsigned g_cntZ;  __device__ volatile unsigned g_genZ;   // full-grid barrier

// ---------------------------------------------------------------------------
// Generation barrier (blocks co-resident by construction)
// ---------------------------------------------------------------------------
__device__ __forceinline__ void bar_sync(unsigned* cnt, volatile unsigned* gen, unsigned n) {
    __syncthreads();
    if (threadIdx.x == 0) {
        __threadfence();
        unsigned g = *gen;
        if (atomicAdd(cnt, 1u) == n - 1u) {
            atomicExch(cnt, 0u);
            __threadfence();
            *gen = g + 1u;
        } else {
            while (*gen == g) { }
        }
        __threadfence();
    }
    __syncthreads();
}

// ---------------------------------------------------------------------------
// Branchless rational tanh (Eigen 13/6 minimax, |err| ~1e-6) with software
// Newton reciprocal (no MUFU, no divergence).
// ---------------------------------------------------------------------------
__device__ __forceinline__ float fast_tanh(float x) {
    float xc = fminf(fmaxf(x, -7.90531110763549805f), 7.90531110763549805f);
    float x2 = xc * xc;
    float p = -2.76076847742355e-16f;
    p = fmaf(p, x2, 2.00018790482477e-13f);
    p = fmaf(p, x2, -8.60467152213735e-11f);
    p = fmaf(p, x2, 5.12229709037114e-08f);
    p = fmaf(p, x2, 1.48572235717979e-05f);
    p = fmaf(p, x2, 6.37261928875436e-04f);
    p = fmaf(p, x2, 4.89352455891786e-03f);
    p *= xc;
    float q = 1.19825839466702e-06f;
    q = fmaf(q, x2, 1.18534705686654e-04f);
    q = fmaf(q, x2, 2.26843463243900e-03f);
    q = fmaf(q, x2, 4.89352518554385e-03f);
    // reciprocal: magic seed + 4 Newton steps (q > 0 always)
    float r = __uint_as_float(0x7EF311C3u - __float_as_uint(q));
    r = r * fmaf(-q, r, 2.0f);
    r = r * fmaf(-q, r, 2.0f);
    r = r * fmaf(-q, r, 2.0f);
    r = r * fmaf(-q, r, 2.0f);
    return p * r;
}
__device__ __forceinline__ float fast_sigmoid(float x) {
    return fmaf(0.5f, fast_tanh(0.5f * x), 0.5f);
}

// ---------------------------------------------------------------------------
// Shared memory union
// ---------------------------------------------------------------------------
#define AS 132                       // smem tile stride (floats)
struct S0 { float a[32 * AS]; float b[32 * AS]; };   // GEMM tiles [k][l] / [k][v]
struct S1 { float h[D_]; float c[D_]; };             // recurrence state
struct S2 { float d[V_]; float vw[V_]; };            // pointer scoring

__global__ void __launch_bounds__(NT, 1)
decoder_kernel(const float* __restrict__ initial_state,
               const float* __restrict__ enc_states,
               const float* __restrict__ seq_points,
               const int*   __restrict__ positions,
               const float* __restrict__ W_ih,
               const float* __restrict__ W_hh,
               const float* __restrict__ b_ih,
               const float* __restrict__ b_hh,
               const float* __restrict__ We_w,
               const float* __restrict__ We_b,
               const float* __restrict__ Wd_w,
               const float* __restrict__ Wd_b,
               const float* __restrict__ v_w,
               const float* __restrict__ v_b,
               float* __restrict__ out_logits,
               float* __restrict__ out_hs,
               float* __restrict__ out_losses)
{
    __shared__ __align__(16) union { S0 s0; S1 s1; S2 s2; } sm;
    __shared__ float red[NW];

    const int tid  = threadIdx.x;
    const int wid  = tid >> 5;
    const int lane = tid & 31;

    // =======================================================================
    // Prologue: convert W_hh (rows 0..8191) + Wd_w (rows 8192..10239) to fp16
    // =======================================================================
    {
        const int NF4_WHH = G4 * (D_ / 4);              // 4,194,304 float4s
        const int NF4_TOT = ROWS_TOT * (D_ / 4);        // 5,242,880 float4s
        for (int i = blockIdx.x * NT + tid; i < NF4_TOT; i += NBLK * NT) {
            float4 v = (i < NF4_WHH) ? ((const float4*)W_hh)[i]
                                     : ((const float4*)Wd_w)[i - NF4_WHH];
            __half2 h01 = __floats2half2_rn(v.x, v.y);
            __half2 h23 = __floats2half2_rn(v.z, v.w);
            uint2 pk;
            pk.x = *(unsigned*)&h01;
            pk.y = *(unsigned*)&h23;
            g_w16[i] = pk;
        }
    }
    bar_sync(&g_cntZ, &g_genZ, NBLK);

    if (blockIdx.x < NA) {
        // ===================================================================
        // Group A: LSTM recurrence. 66 iterations, one group barrier each.
        // Each warp owns 5 rows: gwA + i*2048 (i=0..3 gate rows, i=4 -> d row)
        // ===================================================================
        const int gwA = blockIdx.x * NW + wid;            // 0..2047
        const __half* wbase = (const __half*)g_w16;
        const size_t RSTRIDE = (size_t)2048 * D_;         // halves between row groups

        for (int j = tid; j < D_; j += NT) {
            sm.s1.h[j] = initial_state[j];
            sm.s1.c[j] = 0.0f;
        }
        __syncthreads();

        for (int t = 0; t <= T_; ++t) {
            float x0 = 0.f, x1 = 0.f, x2 = 1.f;
            if (t >= 1 && t <= 64) {
                int pos = positions[t - 1];
                x0 = seq_points[pos * 3 + 0];
                x1 = seq_points[pos * 3 + 1];
                x2 = seq_points[pos * 3 + 2];
            }

            const float4* h4 = (const float4*)sm.s1.h;
            const __half* w0 = wbase + (size_t)gwA * D_;
            float acc[5] = {0.f, 0.f, 0.f, 0.f, 0.f};

            #pragma unroll 2
            for (int kk = lane; kk < D_ / 4; kk += 32) {
                float4 h = h4[kk];
                const __half* wp = w0 + kk * 4;
                #pragma unroll
                for (int i = 0; i < 5; ++i) {
                    uint2 u = *(const uint2*)(wp + (size_t)i * RSTRIDE);
                    __half2 a01 = *(__half2*)&u.x;
                    __half2 a23 = *(__half2*)&u.y;
                    float2 f01 = __half22float2(a01);
                    float2 f23 = __half22float2(a23);
                    acc[i] = fmaf(f01.x, h.x, acc[i]);
                    acc[i] = fmaf(f01.y, h.y, acc[i]);
                    acc[i] = fmaf(f23.x, h.z, acc[i]);
                    acc[i] = fmaf(f23.y, h.w, acc[i]);
                }
            }
            #pragma unroll
            for (int i = 0; i < 5; ++i) {
                float a = acc[i];
                #pragma unroll
                for (int off = 16; off > 0; off >>= 1)
                    a += __shfl_down_sync(0xffffffffu, a, off);
                acc[i] = a;
            }

            if (lane == 0) {
                if (t < T_) {
                    #pragma unroll
                    for (int i = 0; i < 4; ++i) {
                        int r = gwA + i * 2048;
                        float e = b_ih[r] + b_hh[r]
                                + W_ih[r * 3 + 0] * x0
                                + W_ih[r * 3 + 1] * x1
                                + W_ih[r * 3 + 2] * x2;
                        g_gates[t & 1][r] = acc[i] + e;
                    }
                }
                if (t > 0)
                    g_dall[t - 1][gwA] = acc[4] + Wd_b[gwA];
            }

            bar_sync(&g_cntA, &g_genA, NA);

            if (t < T_) {
                const float* gp = g_gates[t & 1];
                for (int j = tid; j < D_; j += NT) {
                    float gi = __ldcg(gp + j);
                    float gf = __ldcg(gp + D_ + j);
                    float gg = __ldcg(gp + 2 * D_ + j);
                    float go = __ldcg(gp + 3 * D_ + j);
                    float i_ = fast_sigmoid(gi);
                    float f_ = fast_sigmoid(gf);
                    float g_ = fast_tanh(gg);
                    float o_ = fast_sigmoid(go);
                    float c  = fmaf(f_, sm.s1.c[j], i_ * g_);
                    float h  = o_ * fast_tanh(c);
                    sm.s1.c[j] = c;
                    sm.s1.h[j] = h;
                    if (blockIdx.x == 0) out_hs[(size_t)t * D_ + j] = h;
                }
                __syncthreads();
            }
        }
    } else {
        // ===================================================================
        // Group B: enc_proj GEMM. 80 tiles of 128l x 128v, one per block.
        // enc_proj[l][v] = sum_k enc[l][k]*We_w[v][k] + We_b[v]
        // ===================================================================
        const int bb = blockIdx.x - NA;
        if (bb < 80) {
            const int l0 = (bb / 16) * 128;
            const int v0 = (bb % 16) * 128;
            const int ty = tid >> 5;          // 0..31 -> l rows ty*4..+3
            const int tx = tid & 31;          // 0..31 -> v cols tx*4..+3
            const int lrow = tid >> 3;        // 0..127 (loader row)
            const int kc4  = tid & 7;         // float4 col within 32-k chunk

            float acc[4][4];
            #pragma unroll
            for (int i = 0; i < 4; ++i)
                #pragma unroll
                for (int j = 0; j < 4; ++j) acc[i][j] = 0.f;

            for (int k0 = 0; k0 < D_; k0 += 32) {
                int gl = l0 + lrow; if (gl > 512) gl = 512;
                float4 av = *(const float4*)&enc_states[(size_t)gl * D_ + k0 + kc4 * 4];
                float4 bv = *(const float4*)&We_w[(size_t)(v0 + lrow) * D_ + k0 + kc4 * 4];
                __syncthreads();
                sm.s0.a[(kc4 * 4 + 0) * AS + lrow] = av.x;
                sm.s0.a[(kc4 * 4 + 1) * AS + lrow] = av.y;
                sm.s0.a[(kc4 * 4 + 2) * AS + lrow] = av.z;
                sm.s0.a[(kc4 * 4 + 3) * AS + lrow] = av.w;
                sm.s0.b[(kc4 * 4 + 0) * AS + lrow] = bv.x;
                sm.s0.b[(kc4 * 4 + 1) * AS + lrow] = bv.y;
                sm.s0.b[(kc4 * 4 + 2) * AS + lrow] = bv.z;
                sm.s0.b[(kc4 * 4 + 3) * AS + lrow] = bv.w;
                __syncthreads();

                #pragma unroll
                for (int k = 0; k < 32; ++k) {
                    float4 a = *(const float4*)&sm.s0.a[k * AS + ty * 4];
                    float4 b = *(const float4*)&sm.s0.b[k * AS + tx * 4];
                    acc[0][0] = fmaf(a.x, b.x, acc[0][0]);
                    acc[0][1] = fmaf(a.x, b.y, acc[0][1]);
                    acc[0][2] = fmaf(a.x, b.z, acc[0][2]);
                    acc[0][3] = fmaf(a.x, b.w, acc[0][3]);
                    acc[1][0] = fmaf(a.y, b.x, acc[1][0]);
                    acc[1][1] = fmaf(a.y, b.y, acc[1][1]);
                    acc[1][2] = fmaf(a.y, b.z, acc[1][2]);
                    acc[1][3] = fmaf(a.y, b.w, acc[1][3]);
                    acc[2][0] = fmaf(a.z, b.x, acc[2][0]);
                    acc[2][1] = fmaf(a.z, b.y, acc[2][1]);
                    acc[2][2] = fmaf(a.z, b.z, acc[2][2]);
                    acc[2][3] = fmaf(a.z, b.w, acc[2][3]);
                    acc[3][0] = fmaf(a.w, b.x, acc[3][0]);
                    acc[3][1] = fmaf(a.w, b.y, acc[3][1]);
                    acc[3][2] = fmaf(a.w, b.z, acc[3][2]);
                    acc[3][3] = fmaf(a.w, b.w, acc[3][3]);
                }
            }

            #pragma unroll
            for (int i = 0; i < 4; ++i) {
                int l = l0 + ty * 4 + i;
                if (l < LP1) {
                    #pragma unroll
                    for (int j = 0; j < 4; ++j) {
                        int v = v0 + tx * 4 + j;
                        g_enc[(size_t)l * V_ + v] = acc[i][j] + We_b[v];
                    }
                }
            }
        }
    }

    bar_sync(&g_cntZ, &g_genZ, NBLK);

    // =======================================================================
    // Stage 2: logits[t][l] = sum_v tanh(enc[l][v] + d_t[v]) * v_w[v] + v_b
    // =======================================================================
    for (int j = tid; j < V_; j += NT) sm.s2.vw[j] = v_w[j];
    const float vb = v_b[0];

    for (int item = blockIdx.x; item < T_ * 9; item += NBLK) {
        const int t  = item / 9;
        const int ch = item % 9;
        __syncthreads();
        for (int j = tid; j < V_; j += NT) sm.s2.d[j] = __ldcg(&g_dall[t][j]);
        __syncthreads();

        const int lbase = ch * 57;
        const float4* d4 = (const float4*)sm.s2.d;
        const float4* w4 = (const float4*)sm.s2.vw;
        for (int l = lbase + wid; l < lbase + 57; l += NW) {
            const float4* e4 = (const float4*)(g_enc + (size_t)l * V_);
            float acc = 0.f;
            #pragma unroll 2
            for (int k = lane; k < V_ / 4; k += 32) {
                float4 e = __ldcg(e4 + k);
                float4 d = d4[k];
                float4 w = w4[k];
                acc = fmaf(fast_tanh(e.x + d.x), w.x, acc);
                acc = fmaf(fast_tanh(e.y + d.y), w.y, acc);
                acc = fmaf(fast_tanh(e.z + d.z), w.z, acc);
                acc = fmaf(fast_tanh(e.w + d.w), w.w, acc);
            }
            #pragma unroll
            for (int off = 16; off > 0; off >>= 1)
                acc += __shfl_down_sync(0xffffffffu, acc, off);
            if (lane == 0) out_logits[(size_t)t * LP1 + l] = acc + vb;
        }
    }

    bar_sync(&g_cntZ, &g_genZ, NBLK);

    // =======================================================================
    // Stage 3: losses[t] = logsumexp(logits_t) - logits_t[target]
    // =======================================================================
    if (blockIdx.x < T_) {
        const int t = blockIdx.x;
        const float* lg = out_logits + (size_t)t * LP1;

        float m = -1e30f;
        for (int i = tid; i < LP1; i += NT) m = fmaxf(m, __ldcg(lg + i));
        #pragma unroll
        for (int off = 16; off > 0; off >>= 1)
            m = fmaxf(m, __shfl_down_sync(0xffffffffu, m, off));
        if (lane == 0) red[wid] = m;
        __syncthreads();
        if (wid == 0) {
            float mm = (lane < NW) ? red[lane] : -1e30f;
            #pragma unroll
            for (int off = 16; off > 0; off >>= 1)
                mm = fmaxf(mm, __shfl_down_sync(0xffffffffu, mm, off));
            if (lane == 0) red[0] = mm;
        }
        __syncthreads();
        m = red[0];
        __syncthreads();

        float s = 0.f;
        for (int i = tid; i < LP1; i += NT) s += expf(__ldcg(lg + i) - m);
        #pragma unroll
        for (int off = 16; off > 0; off >>= 1)
            s += __shfl_down_sync(0xffffffffu, s, off);
        if (lane == 0) red[wid] = s;
        __syncthreads();
        if (wid == 0) {
            float ss = (lane < NW) ? red[lane] : 0.f;
            #pragma unroll
            for (int off = 16; off > 0; off >>= 1)
                ss += __shfl_down_sync(0xffffffffu, ss, off);
            if (lane == 0) {
                int tgt = (t < 64) ? positions[t] : LSEQ;
                out_losses[t] = m + logf(ss) - __ldcg(lg + tgt);
            }
        }
    }
}

// ---------------------------------------------------------------------------
extern "C" void kernel_launch(void* const* d_in, const int* in_sizes, int n_in,
                              void* d_out, int out_size) {
    const float* initial_state = (const float*)d_in[0];
    const float* enc_states    = (const float*)d_in[1];
    const float* seq_points    = (const float*)d_in[2];
    const int*   positions     = (const int*)  d_in[3];
    const float* W_ih          = (const float*)d_in[4];
    const float* W_hh          = (const float*)d_in[5];
    const float* b_ih          = (const float*)d_in[6];
    const float* b_hh          = (const float*)d_in[7];
    const float* We_w          = (const float*)d_in[8];
    const float* We_b          = (const float*)d_in[9];
    const float* Wd_w          = (const float*)d_in[10];
    const float* Wd_b          = (const float*)d_in[11];
    const float* v_w           = (const float*)d_in[12];
    const float* v_b           = (const float*)d_in[13];

    float* out        = (float*)d_out;
    float* out_logits = out;
    float* out_hs     = out + T_ * LP1;
    float* out_losses = out + T_ * LP1 + T_ * D_;

    decoder_kernel<<<NBLK, NT>>>(initial_state, enc_states, seq_points, positions,
                                 W_ih, W_hh, b_ih, b_hh, We_w, We_b, Wd_w, Wd_b,
                                 v_w, v_b, out_logits, out_hs, out_losses);
}

// round 4
// speedup vs baseline: 1.7621x; 1.1135x over previous
#include <cuda_runtime.h>
#include <cuda_fp16.h>
#include <math.h>

// ---------------------------------------------------------------------------
// Problem dims
// ---------------------------------------------------------------------------
#define D_    2048
#define V_    2048
#define LSEQ  512
#define LP1   513
#define T_    65
#define G4    8192
#define ROWS_TOT 10240        // 4D gate rows + V d-rows

#define NBLK  148
#define NT    1024
#define NW    32
#define TOTW  (NBLK*NW)       // 4736 warps

// ---------------------------------------------------------------------------
// Device scratch
// ---------------------------------------------------------------------------
__device__ uint2 g_w16[(size_t)ROWS_TOT * D_ / 4];  // fp16 W_hh + Wd_w (40 MB)
__device__ float g_enc[LP1 * V_];                   // enc_proj
__device__ float g_gates[2][G4];                    // double-buffered gates
__device__ float g_dall[T_][V_];                    // d_t for all steps
__device__ unsigned g_cnt;
__device__ unsigned g_gen;

// ---------------------------------------------------------------------------
// Acquire/release grid barrier (all 148 blocks co-resident)
// ---------------------------------------------------------------------------
__device__ __forceinline__ unsigned ld_acq(const unsigned* p) {
    unsigned v;
    asm volatile("ld.acquire.gpu.global.u32 %0, [%1];" : "=r"(v) : "l"(p) : "memory");
    return v;
}
__device__ __forceinline__ void st_rel(unsigned* p, unsigned v) {
    asm volatile("st.release.gpu.global.u32 [%0], %1;" :: "l"(p), "r"(v) : "memory");
}
__device__ __forceinline__ unsigned atom_add_rel(unsigned* p, unsigned v) {
    unsigned old;
    asm volatile("atom.release.gpu.global.add.u32 %0, [%1], %2;"
                 : "=r"(old) : "l"(p), "r"(v) : "memory");
    return old;
}
__device__ __forceinline__ void gridbar() {
    __syncthreads();
    if (threadIdx.x == 0) {
        unsigned g = ld_acq(&g_gen);
        if (atom_add_rel(&g_cnt, 1u) == NBLK - 1u) {
            atomicExch(&g_cnt, 0u);          // ordered before the release below
            st_rel(&g_gen, g + 1u);
        } else {
            while (ld_acq(&g_gen) == g) { }
        }
    }
    __syncthreads();
}

// ---------------------------------------------------------------------------
// Branchless rational tanh (Eigen 13/6) + Newton reciprocal (no MUFU)
// ---------------------------------------------------------------------------
__device__ __forceinline__ float fast_tanh(float x) {
    float xc = fminf(fmaxf(x, -7.90531110763549805f), 7.90531110763549805f);
    float x2 = xc * xc;
    float p = -2.76076847742355e-16f;
    p = fmaf(p, x2, 2.00018790482477e-13f);
    p = fmaf(p, x2, -8.60467152213735e-11f);
    p = fmaf(p, x2, 5.12229709037114e-08f);
    p = fmaf(p, x2, 1.48572235717979e-05f);
    p = fmaf(p, x2, 6.37261928875436e-04f);
    p = fmaf(p, x2, 4.89352455891786e-03f);
    p *= xc;
    float q = 1.19825839466702e-06f;
    q = fmaf(q, x2, 1.18534705686654e-04f);
    q = fmaf(q, x2, 2.26843463243900e-03f);
    q = fmaf(q, x2, 4.89352518554385e-03f);
    float r = __uint_as_float(0x7EF311C3u - __float_as_uint(q));
    r = r * fmaf(-q, r, 2.0f);
    r = r * fmaf(-q, r, 2.0f);
    r = r * fmaf(-q, r, 2.0f);
    r = r * fmaf(-q, r, 2.0f);
    return p * r;
}
__device__ __forceinline__ float fast_sigmoid(float x) {
    return fmaf(0.5f, fast_tanh(0.5f * x), 0.5f);
}

// fp16 dot8: uint4 = 8 halves vs 8 floats
__device__ __forceinline__ float dot8(uint4 u, float4 ha, float4 hb, float acc) {
    float2 f0 = __half22float2(*(__half2*)&u.x);
    float2 f1 = __half22float2(*(__half2*)&u.y);
    float2 f2 = __half22float2(*(__half2*)&u.z);
    float2 f3 = __half22float2(*(__half2*)&u.w);
    acc = fmaf(f0.x, ha.x, acc);
    acc = fmaf(f0.y, ha.y, acc);
    acc = fmaf(f1.x, ha.z, acc);
    acc = fmaf(f1.y, ha.w, acc);
    acc = fmaf(f2.x, hb.x, acc);
    acc = fmaf(f2.y, hb.y, acc);
    acc = fmaf(f3.x, hb.z, acc);
    acc = fmaf(f3.y, hb.w, acc);
    return acc;
}

// mma.sync m16n8k16 row.col f32.f16.f16.f32
__device__ __forceinline__ void mma16816(float* c, const unsigned* a, const unsigned* b) {
    asm volatile(
        "mma.sync.aligned.m16n8k16.row.col.f32.f16.f16.f32 "
        "{%0,%1,%2,%3}, {%4,%5,%6,%7}, {%8,%9}, {%0,%1,%2,%3};"
        : "+f"(c[0]), "+f"(c[1]), "+f"(c[2]), "+f"(c[3])
        : "r"(a[0]), "r"(a[1]), "r"(a[2]), "r"(a[3]), "r"(b[0]), "r"(b[1]));
}

// ---------------------------------------------------------------------------
// Shared memory union
// ---------------------------------------------------------------------------
#define KS 40                                // half stride per smem tile row
struct S0 { __half a[128 * KS]; __half b[128 * KS]; };   // GEMM tiles
struct S1 { float h[D_]; float c[D_]; };                  // recurrence state
struct S2 { float d[V_]; float vw[V_]; };                 // pointer scoring

__global__ void __launch_bounds__(NT, 1)
decoder_kernel(const float* __restrict__ initial_state,
               const float* __restrict__ enc_states,
               const float* __restrict__ seq_points,
               const int*   __restrict__ positions,
               const float* __restrict__ W_ih,
               const float* __restrict__ W_hh,
               const float* __restrict__ b_ih,
               const float* __restrict__ b_hh,
               const float* __restrict__ We_w,
               const float* __restrict__ We_b,
               const float* __restrict__ Wd_w,
               const float* __restrict__ Wd_b,
               const float* __restrict__ v_w,
               const float* __restrict__ v_b,
               float* __restrict__ out_logits,
               float* __restrict__ out_hs,
               float* __restrict__ out_losses)
{
    __shared__ __align__(16) union { S0 s0; S1 s1; S2 s2; } sm;
    __shared__ float red[NW];

    const int tid  = threadIdx.x;
    const int wid  = tid >> 5;
    const int lane = tid & 31;

    // =======================================================================
    // Phase G: enc_proj GEMM on tensor cores (blocks 0..79, one 128x128 tile)
    //   C[l][v] = sum_k enc[l][k] * We_w[v][k] + We_b[v]
    // =======================================================================
    if (blockIdx.x < 80) {
        const int l0 = (blockIdx.x / 16) * 128;
        const int v0 = (blockIdx.x % 16) * 128;
        const int warpM = wid >> 3;          // 0..3  -> 32 rows
        const int warpN = wid & 7;           // 0..7  -> 16 cols
        const int g  = lane >> 2;
        const int t2 = (lane & 3) * 2;
        const int ldrow = tid >> 3;          // 0..127
        const int ldk   = (tid & 7) * 4;     // 0..28

        float c[2][2][4];
        #pragma unroll
        for (int m = 0; m < 2; ++m)
            #pragma unroll
            for (int n = 0; n < 2; ++n)
                #pragma unroll
                for (int q = 0; q < 4; ++q) c[m][n][q] = 0.f;

        for (int k0 = 0; k0 < D_; k0 += 32) {
            int gl = l0 + ldrow; if (gl > 512) gl = 512;
            float4 av = *(const float4*)&enc_states[(size_t)gl * D_ + k0 + ldk];
            float4 bv = *(const float4*)&We_w[(size_t)(v0 + ldrow) * D_ + k0 + ldk];
            __syncthreads();                 // WAR vs previous chunk compute
            *(__half2*)&sm.s0.a[ldrow * KS + ldk]     = __floats2half2_rn(av.x, av.y);
            *(__half2*)&sm.s0.a[ldrow * KS + ldk + 2] = __floats2half2_rn(av.z, av.w);
            *(__half2*)&sm.s0.b[ldrow * KS + ldk]     = __floats2half2_rn(bv.x, bv.y);
            *(__half2*)&sm.s0.b[ldrow * KS + ldk + 2] = __floats2half2_rn(bv.z, bv.w);
            __syncthreads();

            #pragma unroll
            for (int ks = 0; ks < 2; ++ks) {
                const int kb = ks * 16;
                unsigned a[2][4], b[2][2];
                #pragma unroll
                for (int m = 0; m < 2; ++m) {
                    int ar = warpM * 32 + m * 16;
                    a[m][0] = *(const unsigned*)&sm.s0.a[(ar + g) * KS + kb + t2];
                    a[m][1] = *(const unsigned*)&sm.s0.a[(ar + g + 8) * KS + kb + t2];
                    a[m][2] = *(const unsigned*)&sm.s0.a[(ar + g) * KS + kb + t2 + 8];
                    a[m][3] = *(const unsigned*)&sm.s0.a[(ar + g + 8) * KS + kb + t2 + 8];
                }
                #pragma unroll
                for (int n = 0; n < 2; ++n) {
                    int br = warpN * 16 + n * 8;
                    b[n][0] = *(const unsigned*)&sm.s0.b[(br + g) * KS + kb + t2];
                    b[n][1] = *(const unsigned*)&sm.s0.b[(br + g) * KS + kb + t2 + 8];
                }
                #pragma unroll
                for (int m = 0; m < 2; ++m)
                    #pragma unroll
                    for (int n = 0; n < 2; ++n)
                        mma16816(c[m][n], a[m], b[n]);
            }
        }

        #pragma unroll
        for (int m = 0; m < 2; ++m) {
            #pragma unroll
            for (int n = 0; n < 2; ++n) {
                int lrow = l0 + warpM * 32 + m * 16 + g;
                int vcol = v0 + warpN * 16 + n * 8 + t2;
                if (lrow < LP1) {
                    g_enc[(size_t)lrow * V_ + vcol]     = c[m][n][0] + We_b[vcol];
                    g_enc[(size_t)lrow * V_ + vcol + 1] = c[m][n][1] + We_b[vcol + 1];
                }
                if (lrow + 8 < LP1) {
                    g_enc[(size_t)(lrow + 8) * V_ + vcol]     = c[m][n][2] + We_b[vcol];
                    g_enc[(size_t)(lrow + 8) * V_ + vcol + 1] = c[m][n][3] + We_b[vcol + 1];
                }
            }
        }
    }

    // =======================================================================
    // Phase P: convert W_hh + Wd_w to fp16 (all blocks, grid-strided)
    // =======================================================================
    {
        const int NF4_WHH = G4 * (D_ / 4);
        const int NF4_TOT = ROWS_TOT * (D_ / 4);
        for (int i = blockIdx.x * NT + tid; i < NF4_TOT; i += NBLK * NT) {
            float4 v = (i < NF4_WHH) ? ((const float4*)W_hh)[i]
                                     : ((const float4*)Wd_w)[i - NF4_WHH];
            __half2 h01 = __floats2half2_rn(v.x, v.y);
            __half2 h23 = __floats2half2_rn(v.z, v.w);
            uint2 pk;
            pk.x = *(unsigned*)&h01;
            pk.y = *(unsigned*)&h23;
            g_w16[i] = pk;
        }
    }
    gridbar();

    // =======================================================================
    // Stage 1: LSTM recurrence, all 148 blocks, one barrier per step.
    // Warp gw owns rows: gw, gw+4736, and (if gw%6==0 && gw/6<768) 9472+gw/6.
    // =======================================================================
    {
        const int gw = blockIdx.x * NW + wid;        // 0..4735
        const int r0 = gw;                            // < 8192: always a gate row
        const int r1 = gw + TOTW;                     // 4736..9471: gate or d
        const bool has3 = ((gw % 6) == 0) && ((gw / 6) < 768);
        const int r2 = 9472 + gw / 6;                 // d row

        const __half* wb = (const __half*)g_w16;
        const uint4* w0 = (const uint4*)(wb + (size_t)r0 * D_);
        const uint4* w1 = (const uint4*)(wb + (size_t)r1 * D_);
        const uint4* w2 = (const uint4*)(wb + (size_t)r2 * D_);

        for (int j = tid; j < D_; j += NT) {
            sm.s1.h[j] = initial_state[j];
            sm.s1.c[j] = 0.0f;
        }
        __syncthreads();

        for (int t = 0; t <= T_; ++t) {
            const bool doR0 = (t < T_);                              // gate row
            const bool doR1 = (r1 < G4) ? (t < T_) : (t > 0);        // mixed
            const bool doR2 = has3 && (t > 0);                       // d row

            const float4* h4 = (const float4*)sm.s1.h;
            float a0 = 0.f, a1 = 0.f, a2 = 0.f;

            #pragma unroll 2
            for (int k8 = lane; k8 < 256; k8 += 32) {
                float4 ha = h4[2 * k8];
                float4 hb = h4[2 * k8 + 1];
                if (doR0) a0 = dot8(__ldcg(w0 + k8), ha, hb, a0);
                if (doR1) a1 = dot8(__ldcg(w1 + k8), ha, hb, a1);
                if (doR2) a2 = dot8(__ldcg(w2 + k8), ha, hb, a2);
            }
            #pragma unroll
            for (int off = 16; off > 0; off >>= 1) {
                a0 += __shfl_down_sync(0xffffffffu, a0, off);
                a1 += __shfl_down_sync(0xffffffffu, a1, off);
                a2 += __shfl_down_sync(0xffffffffu, a2, off);
            }

            if (lane == 0) {
                float x0 = 0.f, x1 = 0.f, x2 = 1.f;
                if (t >= 1 && t <= 64) {
                    int pos = positions[t - 1];
                    x0 = seq_points[pos * 3 + 0];
                    x1 = seq_points[pos * 3 + 1];
                    x2 = seq_points[pos * 3 + 2];
                }
                if (doR0) {
                    float e = b_ih[r0] + b_hh[r0]
                            + W_ih[r0 * 3 + 0] * x0
                            + W_ih[r0 * 3 + 1] * x1
                            + W_ih[r0 * 3 + 2] * x2;
                    __stcg(&g_gates[t & 1][r0], a0 + e);
                }
                if (doR1) {
                    if (r1 < G4) {
                        float e = b_ih[r1] + b_hh[r1]
                                + W_ih[r1 * 3 + 0] * x0
                                + W_ih[r1 * 3 + 1] * x1
                                + W_ih[r1 * 3 + 2] * x2;
                        __stcg(&g_gates[t & 1][r1], a1 + e);
                    } else {
                        __stcg(&g_dall[t - 1][r1 - G4], a1 + Wd_b[r1 - G4]);
                    }
                }
                if (doR2)
                    __stcg(&g_dall[t - 1][r2 - G4], a2 + Wd_b[r2 - G4]);
            }

            gridbar();

            if (t < T_) {
                const float* gp = g_gates[t & 1];
                for (int j = tid; j < D_; j += NT) {
                    float gi = __ldcg(gp + j);
                    float gf = __ldcg(gp + D_ + j);
                    float gg = __ldcg(gp + 2 * D_ + j);
                    float go = __ldcg(gp + 3 * D_ + j);
                    float i_ = fast_sigmoid(gi);
                    float f_ = fast_sigmoid(gf);
                    float g_ = fast_tanh(gg);
                    float o_ = fast_sigmoid(go);
                    float c  = fmaf(f_, sm.s1.c[j], i_ * g_);
                    float h  = o_ * fast_tanh(c);
                    sm.s1.c[j] = c;
                    sm.s1.h[j] = h;
                    if (blockIdx.x == 0) out_hs[(size_t)t * D_ + j] = h;
                }
                __syncthreads();
            }
        }
    }

    // =======================================================================
    // Stage 2: logits[t][l] = sum_v tanh(enc[l][v] + d_t[v]) * v_w[v] + v_b
    // =======================================================================
    for (int j = tid; j < V_; j += NT) sm.s2.vw[j] = v_w[j];
    const float vb = v_b[0];

    for (int item = blockIdx.x; item < T_ * 9; item += NBLK) {
        const int t  = item / 9;
        const int ch = item % 9;
        __syncthreads();
        for (int j = tid; j < V_; j += NT) sm.s2.d[j] = __ldcg(&g_dall[t][j]);
        __syncthreads();

        const int lbase = ch * 57;
        const float4* d4 = (const float4*)sm.s2.d;
        const float4* w4 = (const float4*)sm.s2.vw;
        for (int l = lbase + wid; l < lbase + 57; l += NW) {
            const float4* e4 = (const float4*)(g_enc + (size_t)l * V_);
            float acc = 0.f;
            #pragma unroll 2
            for (int k = lane; k < V_ / 4; k += 32) {
                float4 e = __ldcg(e4 + k);
                float4 d = d4[k];
                float4 w = w4[k];
                acc = fmaf(fast_tanh(e.x + d.x), w.x, acc);
                acc = fmaf(fast_tanh(e.y + d.y), w.y, acc);
                acc = fmaf(fast_tanh(e.z + d.z), w.z, acc);
                acc = fmaf(fast_tanh(e.w + d.w), w.w, acc);
            }
            #pragma unroll
            for (int off = 16; off > 0; off >>= 1)
                acc += __shfl_down_sync(0xffffffffu, acc, off);
            if (lane == 0) __stcg(&out_logits[(size_t)t * LP1 + l], acc + vb);
        }
    }

    gridbar();

    // =======================================================================
    // Stage 3: losses
    // =======================================================================
    if (blockIdx.x < T_) {
        const int t = blockIdx.x;
        const float* lg = out_logits + (size_t)t * LP1;

        float m = -1e30f;
        for (int i = tid; i < LP1; i += NT) m = fmaxf(m, __ldcg(lg + i));
        #pragma unroll
        for (int off = 16; off > 0; off >>= 1)
            m = fmaxf(m, __shfl_down_sync(0xffffffffu, m, off));
        if (lane == 0) red[wid] = m;
        __syncthreads();
        if (wid == 0) {
            float mm = (lane < NW) ? red[lane] : -1e30f;
            #pragma unroll
            for (int off = 16; off > 0; off >>= 1)
                mm = fmaxf(mm, __shfl_down_sync(0xffffffffu, mm, off));
            if (lane == 0) red[0] = mm;
        }
        __syncthreads();
        m = red[0];
        __syncthreads();

        float s = 0.f;
        for (int i = tid; i < LP1; i += NT) s += expf(__ldcg(lg + i) - m);
        #pragma unroll
        for (int off = 16; off > 0; off >>= 1)
            s += __shfl_down_sync(0xffffffffu, s, off);
        if (lane == 0) red[wid] = s;
        __syncthreads();
        if (wid == 0) {
            float ss = (lane < NW) ? red[lane] : 0.f;
            #pragma unroll
            for (int off = 16; off > 0; off >>= 1)
                ss += __shfl_down_sync(0xffffffffu, ss, off);
            if (lane == 0) {
                int tgt = (t < 64) ? positions[t] : LSEQ;
                out_losses[t] = m + logf(ss) - __ldcg(lg + tgt);
            }
        }
    }
}

// ---------------------------------------------------------------------------
extern "C" void kernel_launch(void* const* d_in, const int* in_sizes, int n_in,
                              void* d_out, int out_size) {
    const float* initial_state = (const float*)d_in[0];
    const float* enc_states    = (const float*)d_in[1];
    const float* seq_points    = (const float*)d_in[2];
    const int*   positions     = (const int*)  d_in[3];
    const float* W_ih          = (const float*)d_in[4];
    const float* W_hh          = (const float*)d_in[5];
    const float* b_ih          = (const float*)d_in[6];
    const float* b_hh          = (const float*)d_in[7];
    const float* We_w          = (const float*)d_in[8];
    const float* We_b          = (const float*)d_in[9];
    const float* Wd_w          = (const float*)d_in[10];
    const float* Wd_b          = (const float*)d_in[11];
    const float* v_w           = (const float*)d_in[12];
    const float* v_b           = (const float*)d_in[13];

    float* out        = (float*)d_out;
    float* out_logits = out;
    float* out_hs     = out + T_ * LP1;
    float* out_losses = out + T_ * LP1 + T_ * D_;

    decoder_kernel<<<NBLK, NT>>>(initial_state, enc_states, seq_points, positions,
                                 W_ih, W_hh, b_ih, b_hh, We_w, We_b, Wd_w, Wd_b,
                                 v_w, v_b, out_logits, out_hs, out_losses);
}